// round 3
// baseline (speedup 1.0000x reference)
#include <cuda_runtime.h>
#include <cstdint>

#define FEAT      256
#define NBUCKETS  2048
#define CAND_CAP  8192
#define TOP_CAP   8192
#define DEF_INSERT 999000

// ---------------- device scratch (no allocations allowed) ----------------
__device__ uint32_t           g_keys[1 << 20];   // r (23-bit mantissa) per slot
__device__ uint32_t           g_hist[NBUCKETS];
__device__ unsigned long long g_cand[CAND_CAP];  // ((0x7FFFFF - r)<<32) | index
__device__ int                g_ncand;
__device__ uint32_t           g_thresh;          // min r to be a candidate
__device__ uint32_t           g_topidx[TOP_CAP];

// ---------------- Threefry-2x32, 20 rounds (JAX-exact) ----------------
__device__ __forceinline__ uint32_t rotl32(uint32_t x, int d) {
    return (x << d) | (x >> (32 - d));
}

__device__ __forceinline__ void threefry2x32(uint32_t k0, uint32_t k1,
                                             uint32_t x0, uint32_t x1,
                                             uint32_t& o0, uint32_t& o1) {
    const uint32_t ks2 = k0 ^ k1 ^ 0x1BD11BDAu;
    x0 += k0; x1 += k1;
#define TF_R(r) { x0 += x1; x1 = rotl32(x1, (r)); x1 ^= x0; }
    TF_R(13) TF_R(15) TF_R(26) TF_R(6)   x0 += k1;  x1 += ks2 + 1u;
    TF_R(17) TF_R(29) TF_R(16) TF_R(24)  x0 += ks2; x1 += k0  + 2u;
    TF_R(13) TF_R(15) TF_R(26) TF_R(6)   x0 += k0;  x1 += k1  + 3u;
    TF_R(17) TF_R(29) TF_R(16) TF_R(24)  x0 += k1;  x1 += ks2 + 4u;
    TF_R(13) TF_R(15) TF_R(26) TF_R(6)   x0 += ks2; x1 += k0  + 5u;
#undef TF_R
    o0 = x0; o1 = x1;
}

// partitionable-threefry 32-bit bits for element j (hi32(j)==0 for j < 2^32)
__device__ __forceinline__ uint32_t jax_bits32(uint32_t j) {
    uint32_t o0, o1;
    threefry2x32(0u, 42u, 0u, j, o0, o1);
    return o0 ^ o1;   // XOR-fold of the 64-bit block (jax_threefry_partitionable)
}

__device__ __forceinline__ int read_scalar(const int* p, int defv) {
    return p ? p[0] : defv;
}

// ---------------- K0: reset scratch ----------------
__global__ void k_reset() {
    int t = blockIdx.x * blockDim.x + threadIdx.x;
    if (t < NBUCKETS) g_hist[t] = 0;
    if (t == 0) g_ncand = 0;
}

// ---------------- K1: compute r keys + histogram (partitionable threefry) ----------------
__global__ void k_keys_hist(const int* __restrict__ d_size, int max_size, int data_len) {
    __shared__ uint32_t sh[NBUCKETS];
    for (int b = threadIdx.x; b < NBUCKETS; b += blockDim.x) sh[b] = 0;
    __syncthreads();

    int new_size = read_scalar(d_size, max_size) + data_len;
    if (new_size > max_size) new_size = max_size;
    if (new_size < 0) new_size = 0;

    const int stride = gridDim.x * blockDim.x;
    for (int j = blockIdx.x * blockDim.x + threadIdx.x; j < max_size; j += stride) {
        if (j < new_size) {
            uint32_t r = jax_bits32((uint32_t)j) >> 9;  // 23-bit mantissa; monotone w/ uniform
            g_keys[j] = r;
            atomicAdd(&sh[r >> 12], 1u);
        } else {
            g_keys[j] = 0u;
        }
    }
    __syncthreads();
    for (int b = threadIdx.x; b < NBUCKETS; b += blockDim.x) {
        uint32_t c = sh[b];
        if (c) atomicAdd(&g_hist[b], c);
    }
}

// ---------------- K2: find cutoff bucket (descending cumulative >= nsamp) ----------------
__global__ void k_cutoff(int nsamp) {
    if (blockIdx.x == 0 && threadIdx.x == 0) {
        unsigned cum = 0;
        int b = NBUCKETS - 1;
        for (; b >= 0; --b) {
            cum += g_hist[b];
            if ((int)cum >= nsamp) break;
        }
        if (b < 0) b = 0;
        g_thresh = (uint32_t)b << 12;
    }
}

// ---------------- K3: compact candidates above threshold ----------------
__global__ void k_compact(int max_size) {
    const uint32_t thr = g_thresh;
    const int stride = gridDim.x * blockDim.x;
    for (int i = blockIdx.x * blockDim.x + threadIdx.x; i < max_size; i += stride) {
        uint32_t r = g_keys[i];
        if (r >= thr && r != 0u) {
            int pos = atomicAdd(&g_ncand, 1);
            if (pos < CAND_CAP)
                g_cand[pos] = ((unsigned long long)(0x7FFFFFu - r) << 32) | (uint32_t)i;
        }
    }
}

// ---------------- K4: exact rank of each candidate -> ordered top indices ----------------
__global__ void k_rank(int nsamp) {
    int n = g_ncand;
    if (n > CAND_CAP) n = CAND_CAP;
    int t = blockIdx.x * blockDim.x + threadIdx.x;
    if (t >= n) return;
    const unsigned long long mykey = g_cand[t];
    int rank = 0;
    int j = 0;
    // broadcast loop: all threads read the same address each iter (L1 broadcast)
    for (; j + 4 <= n; j += 4) {
        unsigned long long a = g_cand[j];
        unsigned long long b = g_cand[j + 1];
        unsigned long long c = g_cand[j + 2];
        unsigned long long d = g_cand[j + 3];
        rank += (a < mykey) + (b < mykey) + (c < mykey) + (d < mykey);
    }
    for (; j < n; ++j) rank += (g_cand[j] < mykey);
    if (rank < nsamp) g_topidx[rank] = (uint32_t)(mykey & 0xFFFFFFFFu);
}

// ---------------- K5: gather rows, resolving the ring-buffer insert on the fly ----------------
__global__ void k_gather(const float* __restrict__ buf, const float* __restrict__ tr,
                         const int* __restrict__ d_ins, float* __restrict__ out,
                         int max_size, int data_len) {
    int row = blockIdx.x;
    uint32_t t = g_topidx[row];
    long p = (long)(read_scalar(d_ins, DEF_INSERT) % max_size);
    long off = (long)t - p;
    if (off < 0) off += max_size;
    const float4* src = (off < (long)data_len)
        ? (const float4*)(tr + (size_t)off * FEAT)
        : (const float4*)(buf + (size_t)t * FEAT);
    float4* dst = (float4*)(out + (size_t)row * FEAT);
#pragma unroll
    for (int c = threadIdx.x; c < FEAT / 4; c += blockDim.x) dst[c] = src[c];
}

// ---------------- launcher ----------------
extern "C" void kernel_launch(void* const* d_in, const int* in_sizes, int n_in,
                              void* d_out, int out_size) {
    // Classify inputs by element count:
    //   buffer_data: 1,000,000 * 256 = 256,000,000
    //   transition :    64*256*256   =   4,194,304
    //   scalars    : 1-elem entries, metadata order: insert_position, size, sample_batch_size
    int i_buf = -1, i_tr = -1;
    int sc[3] = { -1, -1, -1 };
    int nsc = 0;
    for (int i = 0; i < n_in; ++i) {
        if (in_sizes[i] > 100000000)      i_buf = i;
        else if (in_sizes[i] > 1000000)   i_tr  = i;
        else if (in_sizes[i] >= 1 && in_sizes[i] <= 4 && nsc < 3) sc[nsc++] = i;
    }
    if (i_buf < 0) i_buf = 0;
    if (i_tr  < 0) i_tr  = 1;

    const float* buf   = (const float*)d_in[i_buf];
    const float* tr    = (const float*)d_in[i_tr];
    const int*   d_ins = (sc[0] >= 0) ? (const int*)d_in[sc[0]] : nullptr;
    const int*   d_sz  = (sc[1] >= 0) ? (const int*)d_in[sc[1]] : nullptr;

    int max_size = in_sizes[i_buf] / FEAT;   // 1,000,000
    int data_len = in_sizes[i_tr]  / FEAT;   // 16,384
    int nsamp    = out_size        / FEAT;   // 4,096

    k_reset<<<2, 1024>>>();
    k_keys_hist<<<592, 256>>>(d_sz, max_size, data_len);
    k_cutoff<<<1, 32>>>(nsamp);
    k_compact<<<592, 256>>>(max_size);
    k_rank<<<(CAND_CAP + 255) / 256, 256>>>(nsamp);
    k_gather<<<nsamp, 64>>>(buf, tr, d_ins, (float*)d_out, max_size, data_len);
}

// round 4
// speedup vs baseline: 4.0549x; 4.0549x over previous
#include <cuda_runtime.h>
#include <cstdint>

#define FEAT     256
#define PRE_CAP  16384
#define JT       16
#define JCH      (PRE_CAP / JT)       // 1024 keys per j-chunk
#define DEF_INSERT 999000

typedef unsigned long long u64;

// ---------------- device scratch (no allocations allowed) ----------------
__device__ u64 g_pre[PRE_CAP];        // ((0x7FFFFF - r) << 32) | index
__device__ int g_npre;
__device__ int g_rankp[JT][PRE_CAP];  // partial rank counts per j-tile

// ---------------- Threefry-2x32, 20 rounds, partitionable layout (JAX-exact) ----------------
__device__ __forceinline__ uint32_t rotl32(uint32_t x, int d) {
    return (x << d) | (x >> (32 - d));
}

__device__ __forceinline__ uint32_t jax_bits32(uint32_t j) {
    const uint32_t k0 = 0u, k1 = 42u;
    const uint32_t ks2 = k0 ^ k1 ^ 0x1BD11BDAu;
    uint32_t x0 = 0u + k0, x1 = j + k1;
#define TF_R(r) { x0 += x1; x1 = rotl32(x1, (r)); x1 ^= x0; }
    TF_R(13) TF_R(15) TF_R(26) TF_R(6)   x0 += k1;  x1 += ks2 + 1u;
    TF_R(17) TF_R(29) TF_R(16) TF_R(24)  x0 += ks2; x1 += k0  + 2u;
    TF_R(13) TF_R(15) TF_R(26) TF_R(6)   x0 += k0;  x1 += k1  + 3u;
    TF_R(17) TF_R(29) TF_R(16) TF_R(24)  x0 += k1;  x1 += ks2 + 4u;
    TF_R(13) TF_R(15) TF_R(26) TF_R(6)   x0 += ks2; x1 += k0  + 5u;
#undef TF_R
    return x0 ^ x1;   // XOR-fold (jax_threefry_partitionable)
}

__device__ __forceinline__ int read_scalar(const int* p, int defv) {
    return p ? p[0] : defv;
}

// ---------------- K0: reset counter ----------------
__global__ void k_reset() { g_npre = 0; }

// ---------------- K1: hash all slots, push top-region survivors ----------------
__global__ void k_hash_push(const int* __restrict__ d_size,
                            int max_size, int data_len, int nsamp) {
    int new_size = read_scalar(d_size, max_size) + data_len;
    if (new_size > max_size) new_size = max_size;
    if (new_size < 0) new_size = 0;

    // keep top `keep` mantissa values so expected survivors ~= 1.5 * nsamp
    uint32_t precut = 0u;
    if (new_size > 0) {
        u64 keep = ((u64)nsamp * 3u / 2u) << 23;
        keep /= (u64)new_size;
        precut = (keep >= 0x800000ull) ? 0u : (uint32_t)(0x800000ull - keep);
    }

    const int lane = threadIdx.x & 31;
    const int stride = gridDim.x * blockDim.x;
    for (int j = blockIdx.x * blockDim.x + threadIdx.x;
         j - lane < max_size; j += stride) {
        uint32_t r = 0u;
        bool push = false;
        if (j < new_size) {
            r = jax_bits32((uint32_t)j) >> 9;   // 23-bit mantissa; monotone w/ uniform
            push = (r >= precut);
        }
        unsigned mask = __ballot_sync(0xFFFFFFFFu, push);
        if (mask) {
            int leader = __ffs(mask) - 1;
            int base = 0;
            if (lane == leader) base = atomicAdd(&g_npre, __popc(mask));
            base = __shfl_sync(0xFFFFFFFFu, base, leader);
            if (push) {
                int pos = base + __popc(mask & ((1u << lane) - 1u));
                if (pos < PRE_CAP)
                    g_pre[pos] = ((u64)(0x7FFFFFu - r) << 32) | (uint32_t)j;
            }
        }
    }
}

// ---------------- K2: tiled exact rank (partial counts, smem j-chunks) ----------------
__global__ void k_rank() {
    int npre = g_npre;
    if (npre > PRE_CAP) npre = PRE_CAP;
    if ((int)(blockIdx.x * blockDim.x) >= npre) return;   // uniform per block

    __shared__ u64 sk[JCH];
    int chunk = (npre + JT - 1) / JT;
    int j0 = blockIdx.y * chunk;
    int j1 = j0 + chunk; if (j1 > npre) j1 = npre;
    for (int j = j0 + threadIdx.x; j < j1; j += blockDim.x)
        sk[j - j0] = g_pre[j];
    __syncthreads();

    int t = blockIdx.x * blockDim.x + threadIdx.x;
    u64 mykey = (t < npre) ? g_pre[t] : ~0ull;
    int len = j1 - j0;
    int cnt = 0, j = 0;
    for (; j + 4 <= len; j += 4) {
        cnt += (sk[j]     < mykey);
        cnt += (sk[j + 1] < mykey);
        cnt += (sk[j + 2] < mykey);
        cnt += (sk[j + 3] < mykey);
    }
    for (; j < len; ++j) cnt += (sk[j] < mykey);
    if (t < npre) g_rankp[blockIdx.y][t] = cnt;
}

// ---------------- K3: fused scatter+gather (ring-buffer resolved on the fly) ----------------
__global__ void k_gather(const float* __restrict__ buf, const float* __restrict__ tr,
                         const int* __restrict__ d_ins, float* __restrict__ out,
                         int max_size, int data_len, int nsamp) {
    int t = blockIdx.x;
    int npre = g_npre;
    if (npre > PRE_CAP) npre = PRE_CAP;
    if (t >= npre) return;

    int rank = 0;
#pragma unroll
    for (int jt = 0; jt < JT; ++jt) rank += g_rankp[jt][t];   // L1-broadcast
    if (rank >= nsamp) return;

    uint32_t idx = (uint32_t)g_pre[t];
    long p = (long)(read_scalar(d_ins, DEF_INSERT) % max_size);
    long off = (long)idx - p;
    if (off < 0) off += max_size;
    const float4* src = (off < (long)data_len)
        ? (const float4*)(tr + (size_t)off * FEAT)
        : (const float4*)(buf + (size_t)idx * FEAT);
    float4* dst = (float4*)(out + (size_t)rank * FEAT);
#pragma unroll
    for (int c = threadIdx.x; c < FEAT / 4; c += blockDim.x) dst[c] = src[c];
}

// ---------------- launcher ----------------
extern "C" void kernel_launch(void* const* d_in, const int* in_sizes, int n_in,
                              void* d_out, int out_size) {
    // Classify inputs by element count (robust to ordering):
    int i_buf = -1, i_tr = -1;
    int sc[3] = { -1, -1, -1 };
    int nsc = 0;
    for (int i = 0; i < n_in; ++i) {
        if (in_sizes[i] > 100000000)      i_buf = i;
        else if (in_sizes[i] > 1000000)   i_tr  = i;
        else if (in_sizes[i] >= 1 && in_sizes[i] <= 4 && nsc < 3) sc[nsc++] = i;
    }
    if (i_buf < 0) i_buf = 0;
    if (i_tr  < 0) i_tr  = 1;

    const float* buf   = (const float*)d_in[i_buf];
    const float* tr    = (const float*)d_in[i_tr];
    const int*   d_ins = (sc[0] >= 0) ? (const int*)d_in[sc[0]] : nullptr;
    const int*   d_sz  = (sc[1] >= 0) ? (const int*)d_in[sc[1]] : nullptr;

    int max_size = in_sizes[i_buf] / FEAT;   // 1,000,000
    int data_len = in_sizes[i_tr]  / FEAT;   // 16,384
    int nsamp    = out_size        / FEAT;   // 4,096

    k_reset<<<1, 1>>>();
    k_hash_push<<<512, 256>>>(d_sz, max_size, data_len, nsamp);
    dim3 rgrid(PRE_CAP / 256, JT);
    k_rank<<<rgrid, 256>>>();
    k_gather<<<PRE_CAP, 64>>>(buf, tr, d_ins, (float*)d_out,
                              max_size, data_len, nsamp);
}

// round 5
// speedup vs baseline: 5.7609x; 1.4207x over previous
#include <cuda_runtime.h>
#include <cstdint>

#define FEAT     256
#define PRE_CAP  16384
#define JT       16
#define JCH      (PRE_CAP / JT)
#define DEF_INSERT 999000
#define ROWS_PB  4            // gather rows per block (256 thr / 64 thr-per-row)

typedef unsigned long long u64;

// ---------------- device scratch (no allocations allowed) ----------------
__device__ u64      g_pre[PRE_CAP];        // ((0x7FFFFF - r) << 32) | index
__device__ int      g_npre;                // zero-init; reset at end of each run
__device__ int      g_rankp[JT][PRE_CAP];  // partial rank counts per j-tile
__device__ uint32_t g_topidx[PRE_CAP];     // ordered sampled indices

// ---------------- Threefry-2x32, 20 rounds, partitionable layout (JAX-exact) ----------------
__device__ __forceinline__ uint32_t rotl32(uint32_t x, int d) {
    return (x << d) | (x >> (32 - d));
}

__device__ __forceinline__ uint32_t jax_bits32(uint32_t j) {
    const uint32_t k0 = 0u, k1 = 42u;
    const uint32_t ks2 = k0 ^ k1 ^ 0x1BD11BDAu;
    uint32_t x0 = 0u + k0, x1 = j + k1;
#define TF_R(r) { x0 += x1; x1 = rotl32(x1, (r)); x1 ^= x0; }
    TF_R(13) TF_R(15) TF_R(26) TF_R(6)   x0 += k1;  x1 += ks2 + 1u;
    TF_R(17) TF_R(29) TF_R(16) TF_R(24)  x0 += ks2; x1 += k0  + 2u;
    TF_R(13) TF_R(15) TF_R(26) TF_R(6)   x0 += k0;  x1 += k1  + 3u;
    TF_R(17) TF_R(29) TF_R(16) TF_R(24)  x0 += k1;  x1 += ks2 + 4u;
    TF_R(13) TF_R(15) TF_R(26) TF_R(6)   x0 += ks2; x1 += k0  + 5u;
#undef TF_R
    return x0 ^ x1;   // XOR-fold (jax_threefry_partitionable)
}

__device__ __forceinline__ int read_scalar(const int* p, int defv) {
    return p ? p[0] : defv;
}

// ---------------- K1: hash all slots, push top-region survivors ----------------
__global__ void k_hash_push(const int* __restrict__ d_size,
                            int max_size, int data_len, int nsamp) {
    int new_size = read_scalar(d_size, max_size) + data_len;
    if (new_size > max_size) new_size = max_size;
    if (new_size < 0) new_size = 0;

    // keep top `keep` mantissa values so expected survivors ~= 1.25 * nsamp
    uint32_t precut = 0u;
    if (new_size > 0) {
        u64 keep = ((u64)nsamp * 5u / 4u) << 23;
        keep /= (u64)new_size;
        precut = (keep >= 0x800000ull) ? 0u : (uint32_t)(0x800000ull - keep);
    }

    const int lane = threadIdx.x & 31;
    const int stride = gridDim.x * blockDim.x;
    for (int j = blockIdx.x * blockDim.x + threadIdx.x;
         j - lane < max_size; j += stride) {
        uint32_t r = 0u;
        bool push = false;
        if (j < new_size) {
            r = jax_bits32((uint32_t)j) >> 9;   // 23-bit mantissa; monotone w/ uniform
            push = (r >= precut);
        }
        unsigned mask = __ballot_sync(0xFFFFFFFFu, push);
        if (mask) {
            int leader = __ffs(mask) - 1;
            int base = 0;
            if (lane == leader) base = atomicAdd(&g_npre, __popc(mask));
            base = __shfl_sync(0xFFFFFFFFu, base, leader);
            if (push) {
                int pos = base + __popc(mask & ((1u << lane) - 1u));
                if (pos < PRE_CAP)
                    g_pre[pos] = ((u64)(0x7FFFFFu - r) << 32) | (uint32_t)j;
            }
        }
    }
}

// ---------------- K2: tiled exact rank (partial counts, smem j-chunks) ----------------
__global__ void k_rank() {
    int npre = g_npre;
    if (npre > PRE_CAP) npre = PRE_CAP;
    if ((int)(blockIdx.x * blockDim.x) >= npre) return;   // uniform per block

    __shared__ u64 sk[JCH];
    int chunk = (npre + JT - 1) / JT;
    int j0 = blockIdx.y * chunk;
    int j1 = j0 + chunk; if (j1 > npre) j1 = npre;
    for (int j = j0 + threadIdx.x; j < j1; j += blockDim.x)
        sk[j - j0] = g_pre[j];
    __syncthreads();

    int t = blockIdx.x * blockDim.x + threadIdx.x;
    u64 mykey = (t < npre) ? g_pre[t] : ~0ull;
    int len = j1 - j0;
    int cnt = 0, j = 0;
    for (; j + 4 <= len; j += 4) {
        cnt += (sk[j]     < mykey);
        cnt += (sk[j + 1] < mykey);
        cnt += (sk[j + 2] < mykey);
        cnt += (sk[j + 3] < mykey);
    }
    for (; j < len; ++j) cnt += (sk[j] < mykey);
    if (t < npre) g_rankp[blockIdx.y][t] = cnt;
}

// ---------------- K3: finalize ranks -> ordered index list ----------------
__global__ void k_finalize(int nsamp) {
    int npre = g_npre;
    if (npre > PRE_CAP) npre = PRE_CAP;
    int t = blockIdx.x * blockDim.x + threadIdx.x;
    if (t >= npre) return;

    int rank = 0;
#pragma unroll
    for (int jt = 0; jt < JT; ++jt) rank += g_rankp[jt][t];   // coalesced in t
    if (rank < nsamp) g_topidx[rank] = (uint32_t)g_pre[t];
}

// ---------------- K4: dense gather (ring-buffer resolved on the fly) ----------------
__global__ void k_gather(const float* __restrict__ buf, const float* __restrict__ tr,
                         const int* __restrict__ d_ins, float* __restrict__ out,
                         int max_size, int data_len, int nsamp) {
    // deterministic counter reset for the next invocation/replay
    if (blockIdx.x == 0 && threadIdx.x == 0) g_npre = 0;

    int row = blockIdx.x * ROWS_PB + (threadIdx.x >> 6);
    int c   = threadIdx.x & 63;
    if (row >= nsamp) return;

    uint32_t idx = g_topidx[row];
    long p = (long)(read_scalar(d_ins, DEF_INSERT) % max_size);
    long off = (long)idx - p;
    if (off < 0) off += max_size;
    const float4* src = (off < (long)data_len)
        ? (const float4*)(tr + (size_t)off * FEAT)
        : (const float4*)(buf + (size_t)idx * FEAT);
    ((float4*)(out + (size_t)row * FEAT))[c] = src[c];
}

// ---------------- launcher ----------------
extern "C" void kernel_launch(void* const* d_in, const int* in_sizes, int n_in,
                              void* d_out, int out_size) {
    // Classify inputs by element count (robust to ordering):
    int i_buf = -1, i_tr = -1;
    int sc[3] = { -1, -1, -1 };
    int nsc = 0;
    for (int i = 0; i < n_in; ++i) {
        if (in_sizes[i] > 100000000)      i_buf = i;
        else if (in_sizes[i] > 1000000)   i_tr  = i;
        else if (in_sizes[i] >= 1 && in_sizes[i] <= 4 && nsc < 3) sc[nsc++] = i;
    }
    if (i_buf < 0) i_buf = 0;
    if (i_tr  < 0) i_tr  = 1;

    const float* buf   = (const float*)d_in[i_buf];
    const float* tr    = (const float*)d_in[i_tr];
    const int*   d_ins = (sc[0] >= 0) ? (const int*)d_in[sc[0]] : nullptr;
    const int*   d_sz  = (sc[1] >= 0) ? (const int*)d_in[sc[1]] : nullptr;

    int max_size = in_sizes[i_buf] / FEAT;   // 1,000,000
    int data_len = in_sizes[i_tr]  / FEAT;   // 16,384
    int nsamp    = out_size        / FEAT;   // 4,096

    k_hash_push<<<512, 256>>>(d_sz, max_size, data_len, nsamp);
    dim3 rgrid(PRE_CAP / 256, JT);
    k_rank<<<rgrid, 256>>>();
    k_finalize<<<PRE_CAP / 256, 256>>>(nsamp);
    int gblocks = (nsamp + ROWS_PB - 1) / ROWS_PB;
    k_gather<<<gblocks, ROWS_PB * 64>>>(buf, tr, d_ins, (float*)d_out,
                                        max_size, data_len, nsamp);
}